// round 7
// baseline (speedup 1.0000x reference)
#include <cuda_runtime.h>
#include <math.h>

// Greedy-collapse of the degenerate beam search (prob stays all-ones, beams
// never diverge, tie-break picks beam 0): one persistent kernel, 12 sequential
// steps of GRU -> logits -> softmax/argmax -> write, with hand-rolled grid
// barriers. All cross-CTA globals read via __ldcg (L1 not coherent across SMs).

#define NCTA  148
#define TPB   512
#define NWARP 16
#define VOCAB 16000
#define EDIM  256
#define HDIM  512
#define BATCH 8
#define PAD_ID 0
#define SOS_ID 1
#define EOS_ID 2

__device__ float    g_h[2][BATCH * HDIM];
__device__ float4   g_part[2][NCTA][BATCH];   // x=max, y=sumexp(local max), z=argmax idx (int bits)
__device__ unsigned g_bar;

__global__ void decoder_init(const float* __restrict__ hidden) {
    int t = blockIdx.x * blockDim.x + threadIdx.x;
    if (t < BATCH * HDIM) g_h[0][t] = hidden[t];   // h0 = hidden[0] (1,B,H) contiguous
    if (t == 0) g_bar = 0u;
}

__device__ __forceinline__ void grid_sync(unsigned target) {
    __syncthreads();
    if (threadIdx.x == 0) {
        __threadfence();
        atomicAdd(&g_bar, 1u);
        while (*((volatile unsigned*)&g_bar) < target) { __nanosleep(32); }
        __threadfence();
    }
    __syncthreads();
}

__global__ void __launch_bounds__(TPB, 1) decoder_main(
    const float* __restrict__ embedding,
    const float* __restrict__ w_ih,
    const float* __restrict__ w_hh,
    const float* __restrict__ b_ih,
    const float* __restrict__ b_hh,
    const float* __restrict__ w_out,
    const float* __restrict__ b_out,
    float* __restrict__ out,
    int lenseq)
{
    __shared__ float s_h[BATCH][HDIM];          // 16 KB  h_new staging
    __shared__ float s_log[NWARP][7][BATCH];    // 3.5 KB per-CTA logits
    __shared__ float s_M[BATCH], s_S[BATCH];
    __shared__ int   s_tok[BATCH], s_done[BATCH];

    const int tid  = threadIdx.x;
    const int wp   = tid >> 5;
    const int lane = tid & 31;
    const int cta  = blockIdx.x;
    // contiguous vocab chunk per CTA: first 16 CTAs get 109 rows, rest 108
    const int base  = cta * 108 + (cta < 16 ? cta : 16);
    const int nrows = 108 + (cta < 16 ? 1 : 0);

    if (tid < BATCH) s_tok[tid] = SOS_ID;
    __syncthreads();

    unsigned bar_target = 0;
    int cur = 0;

    for (int step = 0; step < lenseq; ++step) {
        const int nxt = cur ^ 1;

        // ================= Phase A: GRU cell (one warp per (b, j) pair) ======
        for (int t = cta * NWARP + wp; t < BATCH * HDIM; t += NCTA * NWARP) {
            const int b = t >> 9;            // /HDIM
            const int j = t & (HDIM - 1);
            const int tok = s_tok[b];
            const float hold = __ldcg(&g_h[cur][b * HDIM + j]);
            float hv;
            if (tok == PAD_ID || tok == EOS_ID) {
                hv = hold;                   // frozen state for done batch
            } else {
                const float4* e4  = (const float4*)(embedding + (size_t)tok * EDIM);
                const float4* wir = (const float4*)(w_ih + (size_t)j * EDIM);
                const float4* wiz = (const float4*)(w_ih + (size_t)(j + HDIM) * EDIM);
                const float4* win = (const float4*)(w_ih + (size_t)(j + 2 * HDIM) * EDIM);
                float ir = 0.f, iz = 0.f, in_ = 0.f;
                #pragma unroll
                for (int q = 0; q < 2; q++) {
                    const int c = q * 32 + lane;
                    float4 e = e4[c];
                    float4 a = wir[c]; ir  += e.x*a.x + e.y*a.y + e.z*a.z + e.w*a.w;
                    float4 z = wiz[c]; iz  += e.x*z.x + e.y*z.y + e.z*z.z + e.w*z.w;
                    float4 n = win[c]; in_ += e.x*n.x + e.y*n.y + e.z*n.z + e.w*n.w;
                }
                const float4* hp  = (const float4*)(g_h[cur] + b * HDIM);
                const float4* whr = (const float4*)(w_hh + (size_t)j * HDIM);
                const float4* whz = (const float4*)(w_hh + (size_t)(j + HDIM) * HDIM);
                const float4* whn = (const float4*)(w_hh + (size_t)(j + 2 * HDIM) * HDIM);
                float hr = 0.f, hz = 0.f, hn = 0.f;
                #pragma unroll
                for (int q = 0; q < 4; q++) {
                    const int c = q * 32 + lane;
                    float4 h = __ldcg(hp + c);
                    float4 a = whr[c]; hr += h.x*a.x + h.y*a.y + h.z*a.z + h.w*a.w;
                    float4 z = whz[c]; hz += h.x*z.x + h.y*z.y + h.z*z.z + h.w*z.w;
                    float4 n = whn[c]; hn += h.x*n.x + h.y*n.y + h.z*n.z + h.w*n.w;
                }
                #pragma unroll
                for (int off = 16; off; off >>= 1) {
                    ir  += __shfl_xor_sync(0xffffffffu, ir,  off);
                    iz  += __shfl_xor_sync(0xffffffffu, iz,  off);
                    in_ += __shfl_xor_sync(0xffffffffu, in_, off);
                    hr  += __shfl_xor_sync(0xffffffffu, hr,  off);
                    hz  += __shfl_xor_sync(0xffffffffu, hz,  off);
                    hn  += __shfl_xor_sync(0xffffffffu, hn,  off);
                }
                const float rg = 1.f / (1.f + expf(-(ir + b_ih[j]          + hr + b_hh[j])));
                const float zg = 1.f / (1.f + expf(-(iz + b_ih[j + HDIM]   + hz + b_hh[j + HDIM])));
                const float ng = tanhf(in_ + b_ih[j + 2 * HDIM] + rg * (hn + b_hh[j + 2 * HDIM]));
                hv = (1.f - zg) * ng + zg * hold;
            }
            if (lane == 0) g_h[nxt][b * HDIM + j] = hv;
        }
        bar_target += NCTA; grid_sync(bar_target);

        // ================= Phase B1: logits + per-CTA max/sumexp/argmax ======
        {
            const float4* src = (const float4*)g_h[nxt];
            for (int t = tid; t < BATCH * HDIM / 4; t += TPB)
                ((float4*)s_h)[t] = __ldcg(src + t);
        }
        __syncthreads();

        for (int r = wp; r < nrows; r += NWARP) {    // warp per vocab row
            const int row = base + r;
            const float4* wr = (const float4*)(w_out + (size_t)row * HDIM);
            float acc[BATCH];
            #pragma unroll
            for (int b = 0; b < BATCH; b++) acc[b] = 0.f;
            #pragma unroll
            for (int q = 0; q < 4; q++) {
                const int c = q * 32 + lane;
                float4 w4 = wr[c];
                #pragma unroll
                for (int b = 0; b < BATCH; b++) {
                    float4 h4 = ((const float4*)(s_h[b]))[c];
                    acc[b] = fmaf(w4.x, h4.x, fmaf(w4.y, h4.y,
                             fmaf(w4.z, h4.z, fmaf(w4.w, h4.w, acc[b]))));
                }
            }
            #pragma unroll
            for (int off = 16; off; off >>= 1)
                #pragma unroll
                for (int b = 0; b < BATCH; b++)
                    acc[b] += __shfl_xor_sync(0xffffffffu, acc[b], off);
            if (lane == 0) {
                const float bo = b_out[row];
                #pragma unroll
                for (int b = 0; b < BATCH; b++)
                    s_log[wp][r >> 4][b] = acc[b] + bo;
            }
        }
        __syncthreads();

        const int p = step & 1;
        if (wp < BATCH) {                       // warp b reduces batch b over CTA rows
            const int b = wp;
            float m = -INFINITY; int mi = 0x7fffffff;
            for (int r = lane; r < nrows; r += 32) {
                const float v = s_log[r & 15][r >> 4][b];
                if (v > m) { m = v; mi = base + r; }
            }
            #pragma unroll
            for (int off = 16; off; off >>= 1) {
                const float om = __shfl_xor_sync(0xffffffffu, m, off);
                const int   oi = __shfl_xor_sync(0xffffffffu, mi, off);
                if (om > m || (om == m && oi < mi)) { m = om; mi = oi; }
            }
            float s = 0.f;
            for (int r = lane; r < nrows; r += 32)
                s += __expf(s_log[r & 15][r >> 4][b] - m);
            #pragma unroll
            for (int off = 16; off; off >>= 1)
                s += __shfl_xor_sync(0xffffffffu, s, off);
            if (lane == 0)
                g_part[p][cta][b] = make_float4(m, s, __int_as_float(mi), 0.f);
        }
        bar_target += NCTA; grid_sync(bar_target);

        // ================= Phase B2: global reduce (redundant per CTA) + write
        if (wp < BATCH) {
            const int b = wp;
            float m = -INFINITY; int mi = 0x7fffffff;
            for (int c = lane; c < NCTA; c += 32) {
                const float4 pr = __ldcg(&g_part[p][c][b]);
                const int oi = __float_as_int(pr.z);
                if (pr.x > m || (pr.x == m && oi < mi)) { m = pr.x; mi = oi; }
            }
            #pragma unroll
            for (int off = 16; off; off >>= 1) {
                const float om = __shfl_xor_sync(0xffffffffu, m, off);
                const int   oi = __shfl_xor_sync(0xffffffffu, mi, off);
                if (om > m || (om == m && oi < mi)) { m = om; mi = oi; }
            }
            float S = 0.f;
            for (int c = lane; c < NCTA; c += 32) {
                const float4 pr = __ldcg(&g_part[p][c][b]);
                S += pr.y * __expf(pr.x - m);
            }
            #pragma unroll
            for (int off = 16; off; off >>= 1)
                S += __shfl_xor_sync(0xffffffffu, S, off);
            if (lane == 0) {
                const int oldtok = s_tok[b];
                const int d = (oldtok == PAD_ID) || (oldtok == EOS_ID);
                s_done[b] = d;
                s_M[b] = m; s_S[b] = S;
                s_tok[b] = d ? PAD_ID : mi;     // done -> PAD forever
            }
        }
        __syncthreads();

        float* ostep = out + (size_t)step * BATCH * VOCAB;
        for (int b = 0; b < BATCH; b++) {
            const float M   = s_M[b];
            const float inv = 1.0f / s_S[b];
            float* o = ostep + (size_t)b * VOCAB + base;
            if (s_done[b]) {
                for (int r = tid; r < nrows; r += TPB)
                    o[r] = (base + r == PAD_ID) ? 1.0f : 0.0f;   // pad one-hot
            } else {
                for (int r = tid; r < nrows; r += TPB)
                    o[r] = __expf(s_log[r & 15][r >> 4][b] - M) * inv;
            }
        }
        cur = nxt;
    }
}

extern "C" void kernel_launch(void* const* d_in, const int* in_sizes, int n_in,
                              void* d_out, int out_size) {
    const float* hidden    = (const float*)d_in[0];
    const float* embedding = (const float*)d_in[1];
    const float* w_ih      = (const float*)d_in[2];
    const float* w_hh      = (const float*)d_in[3];
    const float* b_ih      = (const float*)d_in[4];
    const float* b_hh      = (const float*)d_in[5];
    const float* w_out     = (const float*)d_in[6];
    const float* b_out     = (const float*)d_in[7];
    float* out = (float*)d_out;
    (void)in_sizes; (void)n_in;

    const int lenseq = out_size / (BATCH * VOCAB);   // host can't read device scalar
    if (lenseq <= 0) return;

    decoder_init<<<16, 256>>>(hidden);
    decoder_main<<<NCTA, TPB>>>(embedding, w_ih, w_hh, b_ih, b_hh,
                                w_out, b_out, out, lenseq);
}

// round 8
// speedup vs baseline: 1.2697x; 1.2697x over previous
#include <cuda_runtime.h>
#include <math.h>

// Greedy-collapsed beam search, persistent-grid decoder.
// Round-8 restructure: TPB=1024 (occ 50%), B1 = 4 rows/warp with packed
// fma.rn.f32x2 over batch pairs + fold-butterfly reduction, GRU reads
// weights exactly once per step (j-per-warp-half), max-free softmax.

#define NCTA  148
#define TPB   1024
#define VOCAB 16000
#define EDIM  256
#define HDIM  512
#define BATCH 8
#define PAD_ID 0
#define SOS_ID 1
#define EOS_ID 2

typedef unsigned long long ull;

__device__ float    g_h[2][BATCH * HDIM];
__device__ float4   g_part[NCTA][BATCH];   // x=max, y=sumexp(abs), z=argmax idx bits
__device__ unsigned g_bar;

__global__ void decoder_init(const float* __restrict__ hidden) {
    int t = blockIdx.x * blockDim.x + threadIdx.x;
    if (t < BATCH * HDIM) g_h[0][t] = hidden[t];
    if (t == 0) g_bar = 0u;
}

__device__ __forceinline__ ull fma2(ull a, ull b, ull c) {
    ull d; asm("fma.rn.f32x2 %0, %1, %2, %3;" : "=l"(d) : "l"(a), "l"(b), "l"(c)); return d;
}
__device__ __forceinline__ ull add2(ull a, ull b) {
    ull d; asm("add.rn.f32x2 %0, %1, %2;" : "=l"(d) : "l"(a), "l"(b)); return d;
}
__device__ __forceinline__ ull bcast2(float x) {
    ull d; asm("mov.b64 %0, {%1, %1};" : "=l"(d) : "r"(__float_as_uint(x))); return d;
}

__device__ __forceinline__ void grid_sync(unsigned target) {
    __syncthreads();
    if (threadIdx.x == 0) {
        __threadfence();
        atomicAdd(&g_bar, 1u);
        while (*(volatile unsigned*)&g_bar < target) {}
        __threadfence();
    }
    __syncthreads();
}

// Stage h (4096 floats) into two smem layouts:
//   s_h03[d] = {h0[d],h1[d],h2[d],h3[d]}, s_h47 likewise  (for B1 packed loads)
//   s_hn[b*516 + d] = h[b][d]                              (for GRU float4 loads)
__device__ __forceinline__ void stage_h(const float* src, float4* s_h03, float4* s_h47,
                                        float* s_hn, int tid) {
    float4 v = __ldcg((const float4*)src + tid);   // tid in [0,1024): one float4 each
    const int b = tid >> 7;
    const int d = (tid & 127) * 4;
    *(float4*)&s_hn[b * 516 + d] = v;
    float* t03 = (b < 4) ? (float*)s_h03 : (float*)s_h47;
    const int bb = b & 3;
    t03[(d + 0) * 4 + bb] = v.x;
    t03[(d + 1) * 4 + bb] = v.y;
    t03[(d + 2) * 4 + bb] = v.z;
    t03[(d + 3) * 4 + bb] = v.w;
}

__global__ void __launch_bounds__(TPB, 1) decoder_main(
    const float* __restrict__ embedding,
    const float* __restrict__ w_ih,
    const float* __restrict__ w_hh,
    const float* __restrict__ b_ih,
    const float* __restrict__ b_hh,
    const float* __restrict__ w_out,
    const float* __restrict__ b_out,
    float* __restrict__ out,
    int lenseq)
{
    __shared__ float4 s_h03[HDIM];            // 8 KB
    __shared__ float4 s_h47[HDIM];            // 8 KB
    __shared__ float  s_hn[BATCH * 516];      // 16.1 KB (516 = pad for bank spread)
    __shared__ float  s_log[112][9];          // 4 KB, stride-9 = conflict-free
    __shared__ float  s_S[BATCH];
    __shared__ int    s_tok[BATCH], s_done[BATCH];

    const int tid  = threadIdx.x;
    const int wp   = tid >> 5;
    const int lane = tid & 31;
    const int cta  = blockIdx.x;
    const int base  = cta * 108 + (cta < 16 ? cta : 16);
    const int nrows = 108 + (cta < 16 ? 1 : 0);

    // GRU task: 1024 tasks = 512 j's x 2 batch-halves, spread across CTAs
    const int  task   = wp * NCTA + cta;
    const bool gru_on = task < 2 * HDIM;
    const int  gj     = task >> 1;
    const int  gb     = (task & 1) * 4 + (lane >> 3);  // batch
    const int  gg     = lane & 7;                       // dim group

    if (tid < BATCH) s_tok[tid] = SOS_ID;
    stage_h(g_h[0], s_h03, s_h47, s_hn, tid);
    __syncthreads();

    unsigned bt = 0;
    int cur = 0;

    for (int step = 0; step < lenseq; ++step) {
        const int nxt = cur ^ 1;

        // ================= Phase A: GRU (weights read once chip-wide) ========
        if (gru_on) {
            const int tok = s_tok[gb];
            float ir = 0.f, iz = 0.f, in_ = 0.f;
            const float4* e4  = (const float4*)(embedding + (size_t)tok * EDIM);
            const float4* air = (const float4*)(w_ih + (size_t)gj * EDIM);
            const float4* aiz = (const float4*)(w_ih + (size_t)(gj + HDIM) * EDIM);
            const float4* ain = (const float4*)(w_ih + (size_t)(gj + 2 * HDIM) * EDIM);
            #pragma unroll
            for (int it = 0; it < 8; ++it) {
                const int c = gg * 8 + it;
                float4 e = e4[c];
                float4 a = air[c]; ir  += e.x*a.x + e.y*a.y + e.z*a.z + e.w*a.w;
                float4 z = aiz[c]; iz  += e.x*z.x + e.y*z.y + e.z*z.z + e.w*z.w;
                float4 n = ain[c]; in_ += e.x*n.x + e.y*n.y + e.z*n.z + e.w*n.w;
            }
            float hr = 0.f, hz = 0.f, hn = 0.f;
            const float4* uhr = (const float4*)(w_hh + (size_t)gj * HDIM);
            const float4* uhz = (const float4*)(w_hh + (size_t)(gj + HDIM) * HDIM);
            const float4* uhn = (const float4*)(w_hh + (size_t)(gj + 2 * HDIM) * HDIM);
            const float*  hb  = s_hn + gb * 516;
            #pragma unroll 4
            for (int it = 0; it < 16; ++it) {
                const int c = gg * 16 + it;
                float4 h = *(const float4*)&hb[c * 4];
                float4 a = uhr[c]; hr += h.x*a.x + h.y*a.y + h.z*a.z + h.w*a.w;
                float4 z = uhz[c]; hz += h.x*z.x + h.y*z.y + h.z*z.z + h.w*z.w;
                float4 n = uhn[c]; hn += h.x*n.x + h.y*n.y + h.z*n.z + h.w*n.w;
            }
            #pragma unroll
            for (int off = 1; off < 8; off <<= 1) {
                ir  += __shfl_xor_sync(~0u, ir,  off);
                iz  += __shfl_xor_sync(~0u, iz,  off);
                in_ += __shfl_xor_sync(~0u, in_, off);
                hr  += __shfl_xor_sync(~0u, hr,  off);
                hz  += __shfl_xor_sync(~0u, hz,  off);
                hn  += __shfl_xor_sync(~0u, hn,  off);
            }
            if (gg == 0) {
                const float hold = hb[gj];
                float hv;
                if (tok == PAD_ID || tok == EOS_ID) {
                    hv = hold;
                } else {
                    const float rg = 1.f / (1.f + expf(-(ir + b_ih[gj]            + hr + b_hh[gj])));
                    const float zg = 1.f / (1.f + expf(-(iz + b_ih[gj + HDIM]     + hz + b_hh[gj + HDIM])));
                    const float ng = tanhf(in_ + b_ih[gj + 2 * HDIM] + rg * (hn + b_hh[gj + 2 * HDIM]));
                    hv = (1.f - zg) * ng + zg * hold;
                }
                g_h[nxt][gb * HDIM + gj] = hv;
            }
        }
        bt += NCTA; grid_sync(bt);

        // ================= Stage h(nxt) into smem ============================
        stage_h(g_h[nxt], s_h03, s_h47, s_hn, tid);
        __syncthreads();

        // ================= Phase B1: logits, 4 rows/warp, packed f32x2 =======
        {
            const int r0c = min(wp,      nrows - 1);
            const int r1c = min(wp + 32, nrows - 1);
            const int r2c = min(wp + 64, nrows - 1);
            const int r3c = min(wp + 96, nrows - 1);
            const float* w0 = w_out + (size_t)(base + r0c) * HDIM;
            const float* w1 = w_out + (size_t)(base + r1c) * HDIM;
            const float* w2 = w_out + (size_t)(base + r2c) * HDIM;
            const float* w3 = w_out + (size_t)(base + r3c) * HDIM;
            ull v[16];
            #pragma unroll
            for (int i = 0; i < 16; i++) v[i] = 0ull;
            #pragma unroll 4
            for (int k = 0; k < 16; k++) {
                const int d = k * 32 + lane;                       // coalesced dims
                const ulonglong2 hA = *(const ulonglong2*)&s_h03[d];  // {h01,h23}
                const ulonglong2 hB = *(const ulonglong2*)&s_h47[d];  // {h45,h67}
                ull wb;
                wb = bcast2(w0[d]);
                v[0]=fma2(wb,hA.x,v[0]);  v[1]=fma2(wb,hA.y,v[1]);
                v[2]=fma2(wb,hB.x,v[2]);  v[3]=fma2(wb,hB.y,v[3]);
                wb = bcast2(w1[d]);
                v[4]=fma2(wb,hA.x,v[4]);  v[5]=fma2(wb,hA.y,v[5]);
                v[6]=fma2(wb,hB.x,v[6]);  v[7]=fma2(wb,hB.y,v[7]);
                wb = bcast2(w2[d]);
                v[8]=fma2(wb,hA.x,v[8]);  v[9]=fma2(wb,hA.y,v[9]);
                v[10]=fma2(wb,hB.x,v[10]); v[11]=fma2(wb,hB.y,v[11]);
                wb = bcast2(w3[d]);
                v[12]=fma2(wb,hA.x,v[12]); v[13]=fma2(wb,hA.y,v[13]);
                v[14]=fma2(wb,hB.x,v[14]); v[15]=fma2(wb,hB.y,v[15]);
            }
            // fold-butterfly: 16 accs x 32 lanes -> each lane-pair one total
            #pragma unroll
            for (int i = 0; i < 8; i++) {
                ull give = (lane & 16) ? v[i] : v[i + 8];
                ull keep = (lane & 16) ? v[i + 8] : v[i];
                v[i] = add2(keep, __shfl_xor_sync(~0u, give, 16));
            }
            #pragma unroll
            for (int i = 0; i < 4; i++) {
                ull give = (lane & 8) ? v[i] : v[i + 4];
                ull keep = (lane & 8) ? v[i + 4] : v[i];
                v[i] = add2(keep, __shfl_xor_sync(~0u, give, 8));
            }
            #pragma unroll
            for (int i = 0; i < 2; i++) {
                ull give = (lane & 4) ? v[i] : v[i + 2];
                ull keep = (lane & 4) ? v[i + 2] : v[i];
                v[i] = add2(keep, __shfl_xor_sync(~0u, give, 4));
            }
            {
                ull give = (lane & 2) ? v[0] : v[1];
                ull keep = (lane & 2) ? v[1] : v[0];
                v[0] = add2(keep, __shfl_xor_sync(~0u, give, 2));
            }
            v[0] = add2(v[0], __shfl_xor_sync(~0u, v[0], 1));
            // lane l holds total for row index (l>>3)&3, batch-pair (l>>1)&3
            if (!(lane & 1)) {
                const int i = (lane >> 3) & 3;
                const int p = (lane >> 1) & 3;
                const int r = wp + 32 * i;
                if (r < nrows) {
                    const float bo = b_out[base + r];
                    const float2 lv = *(float2*)&v[0];
                    s_log[r][2 * p]     = lv.x + bo;
                    s_log[r][2 * p + 1] = lv.y + bo;
                }
            }
        }
        __syncthreads();

        // ============ per-CTA partial: abs-sumexp + argmax (warps 0-7) =======
        if (wp < BATCH) {
            const int b = wp;
            float m = -INFINITY, s = 0.f; int mi = 0x7fffffff;
            for (int r = lane; r < nrows; r += 32) {
                const float vv = s_log[r][b];
                s += __expf(vv);
                if (vv > m) { m = vv; mi = base + r; }
            }
            #pragma unroll
            for (int off = 16; off; off >>= 1) {
                const float om = __shfl_xor_sync(~0u, m, off);
                const int   oi = __shfl_xor_sync(~0u, mi, off);
                s += __shfl_xor_sync(~0u, s, off);
                if (om > m || (om == m && oi < mi)) { m = om; mi = oi; }
            }
            if (lane == 0) g_part[cta][b] = make_float4(m, s, __int_as_float(mi), 0.f);
        }
        bt += NCTA; grid_sync(bt);

        // ============ Phase B2: global reduce (redundant per CTA) ============
        if (wp < BATCH) {
            const int b = wp;
            float m = -INFINITY, S = 0.f; int mi = 0x7fffffff;
            for (int c = lane; c < NCTA; c += 32) {
                const float4 pr = __ldcg(&g_part[c][b]);
                S += pr.y;
                const int oi = __float_as_int(pr.z);
                if (pr.x > m || (pr.x == m && oi < mi)) { m = pr.x; mi = oi; }
            }
            #pragma unroll
            for (int off = 16; off; off >>= 1) {
                const float om = __shfl_xor_sync(~0u, m, off);
                const int   oi = __shfl_xor_sync(~0u, mi, off);
                S += __shfl_xor_sync(~0u, S, off);
                if (om > m || (om == m && oi < mi)) { m = om; mi = oi; }
            }
            if (lane == 0) {
                const int old = s_tok[b];
                const int d = (old == PAD_ID) | (old == EOS_ID);
                s_done[b] = d;
                s_S[b]    = S;
                s_tok[b]  = d ? PAD_ID : mi;    // done -> PAD forever
            }
        }
        __syncthreads();

        // ============ Phase C: coalesced probability write ===================
        {
            const int b  = tid >> 7;        // 8 groups of 128 threads
            const int rr = tid & 127;
            if (rr < nrows) {
                float* o = out + ((size_t)step * BATCH + b) * VOCAB + base;
                if (s_done[b]) o[rr] = (base + rr == PAD_ID) ? 1.f : 0.f;
                else           o[rr] = __fdividef(__expf(s_log[rr][b]), s_S[b]);
            }
        }
        cur = nxt;
    }
}

extern "C" void kernel_launch(void* const* d_in, const int* in_sizes, int n_in,
                              void* d_out, int out_size) {
    const float* hidden    = (const float*)d_in[0];
    const float* embedding = (const float*)d_in[1];
    const float* w_ih      = (const float*)d_in[2];
    const float* w_hh      = (const float*)d_in[3];
    const float* b_ih      = (const float*)d_in[4];
    const float* b_hh      = (const float*)d_in[5];
    const float* w_out     = (const float*)d_in[6];
    const float* b_out     = (const float*)d_in[7];
    float* out = (float*)d_out;
    (void)in_sizes; (void)n_in;

    const int lenseq = out_size / (BATCH * VOCAB);
    if (lenseq <= 0) return;

    decoder_init<<<16, 256>>>(hidden);
    decoder_main<<<NCTA, TPB>>>(embedding, w_ih, w_hh, b_ih, b_hh,
                                w_out, b_out, out, lenseq);
}

// round 9
// speedup vs baseline: 1.2776x; 1.0063x over previous
#include <cuda_runtime.h>
#include <math.h>

// Greedy-collapsed beam search, persistent-grid decoder.
// Round-8 restructure: TPB=1024 (occ 50%), B1 = 4 rows/warp with packed
// fma.rn.f32x2 over batch pairs + fold-butterfly reduction, GRU reads
// weights exactly once per step (j-per-warp-half), max-free softmax.

#define NCTA  148
#define TPB   1024
#define VOCAB 16000
#define EDIM  256
#define HDIM  512
#define BATCH 8
#define PAD_ID 0
#define SOS_ID 1
#define EOS_ID 2

typedef unsigned long long ull;

__device__ float    g_h[2][BATCH * HDIM];
__device__ float4   g_part[NCTA][BATCH];   // x=max, y=sumexp(abs), z=argmax idx bits
__device__ unsigned g_bar;

__global__ void decoder_init(const float* __restrict__ hidden) {
    int t = blockIdx.x * blockDim.x + threadIdx.x;
    if (t < BATCH * HDIM) g_h[0][t] = hidden[t];
    if (t == 0) g_bar = 0u;
}

__device__ __forceinline__ ull fma2(ull a, ull b, ull c) {
    ull d; asm("fma.rn.f32x2 %0, %1, %2, %3;" : "=l"(d) : "l"(a), "l"(b), "l"(c)); return d;
}
__device__ __forceinline__ ull add2(ull a, ull b) {
    ull d; asm("add.rn.f32x2 %0, %1, %2;" : "=l"(d) : "l"(a), "l"(b)); return d;
}
__device__ __forceinline__ ull bcast2(float x) {
    ull d; asm("mov.b64 %0, {%1, %1};" : "=l"(d) : "r"(__float_as_uint(x))); return d;
}

__device__ __forceinline__ void grid_sync(unsigned target) {
    __syncthreads();
    if (threadIdx.x == 0) {
        __threadfence();
        atomicAdd(&g_bar, 1u);
        while (*(volatile unsigned*)&g_bar < target) {}
        __threadfence();
    }
    __syncthreads();
}

// Stage h (4096 floats) into two smem layouts:
//   s_h03[d] = {h0[d],h1[d],h2[d],h3[d]}, s_h47 likewise  (for B1 packed loads)
//   s_hn[b*516 + d] = h[b][d]                              (for GRU float4 loads)
__device__ __forceinline__ void stage_h(const float* src, float4* s_h03, float4* s_h47,
                                        float* s_hn, int tid) {
    float4 v = __ldcg((const float4*)src + tid);   // tid in [0,1024): one float4 each
    const int b = tid >> 7;
    const int d = (tid & 127) * 4;
    *(float4*)&s_hn[b * 516 + d] = v;
    float* t03 = (b < 4) ? (float*)s_h03 : (float*)s_h47;
    const int bb = b & 3;
    t03[(d + 0) * 4 + bb] = v.x;
    t03[(d + 1) * 4 + bb] = v.y;
    t03[(d + 2) * 4 + bb] = v.z;
    t03[(d + 3) * 4 + bb] = v.w;
}

__global__ void __launch_bounds__(TPB, 1) decoder_main(
    const float* __restrict__ embedding,
    const float* __restrict__ w_ih,
    const float* __restrict__ w_hh,
    const float* __restrict__ b_ih,
    const float* __restrict__ b_hh,
    const float* __restrict__ w_out,
    const float* __restrict__ b_out,
    float* __restrict__ out,
    int lenseq)
{
    __shared__ float4 s_h03[HDIM];            // 8 KB
    __shared__ float4 s_h47[HDIM];            // 8 KB
    __shared__ float  s_hn[BATCH * 516];      // 16.1 KB (516 = pad for bank spread)
    __shared__ float  s_log[112][9];          // 4 KB, stride-9 = conflict-free
    __shared__ float  s_S[BATCH];
    __shared__ int    s_tok[BATCH], s_done[BATCH];

    const int tid  = threadIdx.x;
    const int wp   = tid >> 5;
    const int lane = tid & 31;
    const int cta  = blockIdx.x;
    const int base  = cta * 108 + (cta < 16 ? cta : 16);
    const int nrows = 108 + (cta < 16 ? 1 : 0);

    // GRU task: 1024 tasks = 512 j's x 2 batch-halves, spread across CTAs
    const int  task   = wp * NCTA + cta;
    const bool gru_on = task < 2 * HDIM;
    const int  gj     = task >> 1;
    const int  gb     = (task & 1) * 4 + (lane >> 3);  // batch
    const int  gg     = lane & 7;                       // dim group

    if (tid < BATCH) s_tok[tid] = SOS_ID;
    stage_h(g_h[0], s_h03, s_h47, s_hn, tid);
    __syncthreads();

    unsigned bt = 0;
    int cur = 0;

    for (int step = 0; step < lenseq; ++step) {
        const int nxt = cur ^ 1;

        // ================= Phase A: GRU (weights read once chip-wide) ========
        if (gru_on) {
            const int tok = s_tok[gb];
            float ir = 0.f, iz = 0.f, in_ = 0.f;
            const float4* e4  = (const float4*)(embedding + (size_t)tok * EDIM);
            const float4* air = (const float4*)(w_ih + (size_t)gj * EDIM);
            const float4* aiz = (const float4*)(w_ih + (size_t)(gj + HDIM) * EDIM);
            const float4* ain = (const float4*)(w_ih + (size_t)(gj + 2 * HDIM) * EDIM);
            #pragma unroll
            for (int it = 0; it < 8; ++it) {
                const int c = gg * 8 + it;
                float4 e = e4[c];
                float4 a = air[c]; ir  += e.x*a.x + e.y*a.y + e.z*a.z + e.w*a.w;
                float4 z = aiz[c]; iz  += e.x*z.x + e.y*z.y + e.z*z.z + e.w*z.w;
                float4 n = ain[c]; in_ += e.x*n.x + e.y*n.y + e.z*n.z + e.w*n.w;
            }
            float hr = 0.f, hz = 0.f, hn = 0.f;
            const float4* uhr = (const float4*)(w_hh + (size_t)gj * HDIM);
            const float4* uhz = (const float4*)(w_hh + (size_t)(gj + HDIM) * HDIM);
            const float4* uhn = (const float4*)(w_hh + (size_t)(gj + 2 * HDIM) * HDIM);
            const float*  hb  = s_hn + gb * 516;
            #pragma unroll 4
            for (int it = 0; it < 16; ++it) {
                const int c = gg * 16 + it;
                float4 h = *(const float4*)&hb[c * 4];
                float4 a = uhr[c]; hr += h.x*a.x + h.y*a.y + h.z*a.z + h.w*a.w;
                float4 z = uhz[c]; hz += h.x*z.x + h.y*z.y + h.z*z.z + h.w*z.w;
                float4 n = uhn[c]; hn += h.x*n.x + h.y*n.y + h.z*n.z + h.w*n.w;
            }
            #pragma unroll
            for (int off = 1; off < 8; off <<= 1) {
                ir  += __shfl_xor_sync(~0u, ir,  off);
                iz  += __shfl_xor_sync(~0u, iz,  off);
                in_ += __shfl_xor_sync(~0u, in_, off);
                hr  += __shfl_xor_sync(~0u, hr,  off);
                hz  += __shfl_xor_sync(~0u, hz,  off);
                hn  += __shfl_xor_sync(~0u, hn,  off);
            }
            if (gg == 0) {
                const float hold = hb[gj];
                float hv;
                if (tok == PAD_ID || tok == EOS_ID) {
                    hv = hold;
                } else {
                    const float rg = 1.f / (1.f + expf(-(ir + b_ih[gj]            + hr + b_hh[gj])));
                    const float zg = 1.f / (1.f + expf(-(iz + b_ih[gj + HDIM]     + hz + b_hh[gj + HDIM])));
                    const float ng = tanhf(in_ + b_ih[gj + 2 * HDIM] + rg * (hn + b_hh[gj + 2 * HDIM]));
                    hv = (1.f - zg) * ng + zg * hold;
                }
                g_h[nxt][gb * HDIM + gj] = hv;
            }
        }
        bt += NCTA; grid_sync(bt);

        // ================= Stage h(nxt) into smem ============================
        stage_h(g_h[nxt], s_h03, s_h47, s_hn, tid);
        __syncthreads();

        // ================= Phase B1: logits, 4 rows/warp, packed f32x2 =======
        {
            const int r0c = min(wp,      nrows - 1);
            const int r1c = min(wp + 32, nrows - 1);
            const int r2c = min(wp + 64, nrows - 1);
            const int r3c = min(wp + 96, nrows - 1);
            const float* w0 = w_out + (size_t)(base + r0c) * HDIM;
            const float* w1 = w_out + (size_t)(base + r1c) * HDIM;
            const float* w2 = w_out + (size_t)(base + r2c) * HDIM;
            const float* w3 = w_out + (size_t)(base + r3c) * HDIM;
            ull v[16];
            #pragma unroll
            for (int i = 0; i < 16; i++) v[i] = 0ull;
            #pragma unroll 4
            for (int k = 0; k < 16; k++) {
                const int d = k * 32 + lane;                       // coalesced dims
                const ulonglong2 hA = *(const ulonglong2*)&s_h03[d];  // {h01,h23}
                const ulonglong2 hB = *(const ulonglong2*)&s_h47[d];  // {h45,h67}
                ull wb;
                wb = bcast2(w0[d]);
                v[0]=fma2(wb,hA.x,v[0]);  v[1]=fma2(wb,hA.y,v[1]);
                v[2]=fma2(wb,hB.x,v[2]);  v[3]=fma2(wb,hB.y,v[3]);
                wb = bcast2(w1[d]);
                v[4]=fma2(wb,hA.x,v[4]);  v[5]=fma2(wb,hA.y,v[5]);
                v[6]=fma2(wb,hB.x,v[6]);  v[7]=fma2(wb,hB.y,v[7]);
                wb = bcast2(w2[d]);
                v[8]=fma2(wb,hA.x,v[8]);  v[9]=fma2(wb,hA.y,v[9]);
                v[10]=fma2(wb,hB.x,v[10]); v[11]=fma2(wb,hB.y,v[11]);
                wb = bcast2(w3[d]);
                v[12]=fma2(wb,hA.x,v[12]); v[13]=fma2(wb,hA.y,v[13]);
                v[14]=fma2(wb,hB.x,v[14]); v[15]=fma2(wb,hB.y,v[15]);
            }
            // fold-butterfly: 16 accs x 32 lanes -> each lane-pair one total
            #pragma unroll
            for (int i = 0; i < 8; i++) {
                ull give = (lane & 16) ? v[i] : v[i + 8];
                ull keep = (lane & 16) ? v[i + 8] : v[i];
                v[i] = add2(keep, __shfl_xor_sync(~0u, give, 16));
            }
            #pragma unroll
            for (int i = 0; i < 4; i++) {
                ull give = (lane & 8) ? v[i] : v[i + 4];
                ull keep = (lane & 8) ? v[i + 4] : v[i];
                v[i] = add2(keep, __shfl_xor_sync(~0u, give, 8));
            }
            #pragma unroll
            for (int i = 0; i < 2; i++) {
                ull give = (lane & 4) ? v[i] : v[i + 2];
                ull keep = (lane & 4) ? v[i + 2] : v[i];
                v[i] = add2(keep, __shfl_xor_sync(~0u, give, 4));
            }
            {
                ull give = (lane & 2) ? v[0] : v[1];
                ull keep = (lane & 2) ? v[1] : v[0];
                v[0] = add2(keep, __shfl_xor_sync(~0u, give, 2));
            }
            v[0] = add2(v[0], __shfl_xor_sync(~0u, v[0], 1));
            // lane l holds total for row index (l>>3)&3, batch-pair (l>>1)&3
            if (!(lane & 1)) {
                const int i = (lane >> 3) & 3;
                const int p = (lane >> 1) & 3;
                const int r = wp + 32 * i;
                if (r < nrows) {
                    const float bo = b_out[base + r];
                    const float2 lv = *(float2*)&v[0];
                    s_log[r][2 * p]     = lv.x + bo;
                    s_log[r][2 * p + 1] = lv.y + bo;
                }
            }
        }
        __syncthreads();

        // ============ per-CTA partial: abs-sumexp + argmax (warps 0-7) =======
        if (wp < BATCH) {
            const int b = wp;
            float m = -INFINITY, s = 0.f; int mi = 0x7fffffff;
            for (int r = lane; r < nrows; r += 32) {
                const float vv = s_log[r][b];
                s += __expf(vv);
                if (vv > m) { m = vv; mi = base + r; }
            }
            #pragma unroll
            for (int off = 16; off; off >>= 1) {
                const float om = __shfl_xor_sync(~0u, m, off);
                const int   oi = __shfl_xor_sync(~0u, mi, off);
                s += __shfl_xor_sync(~0u, s, off);
                if (om > m || (om == m && oi < mi)) { m = om; mi = oi; }
            }
            if (lane == 0) g_part[cta][b] = make_float4(m, s, __int_as_float(mi), 0.f);
        }
        bt += NCTA; grid_sync(bt);

        // ============ Phase B2: global reduce (redundant per CTA) ============
        if (wp < BATCH) {
            const int b = wp;
            float m = -INFINITY, S = 0.f; int mi = 0x7fffffff;
            for (int c = lane; c < NCTA; c += 32) {
                const float4 pr = __ldcg(&g_part[c][b]);
                S += pr.y;
                const int oi = __float_as_int(pr.z);
                if (pr.x > m || (pr.x == m && oi < mi)) { m = pr.x; mi = oi; }
            }
            #pragma unroll
            for (int off = 16; off; off >>= 1) {
                const float om = __shfl_xor_sync(~0u, m, off);
                const int   oi = __shfl_xor_sync(~0u, mi, off);
                S += __shfl_xor_sync(~0u, S, off);
                if (om > m || (om == m && oi < mi)) { m = om; mi = oi; }
            }
            if (lane == 0) {
                const int old = s_tok[b];
                const int d = (old == PAD_ID) | (old == EOS_ID);
                s_done[b] = d;
                s_S[b]    = S;
                s_tok[b]  = d ? PAD_ID : mi;    // done -> PAD forever
            }
        }
        __syncthreads();

        // ============ Phase C: coalesced probability write ===================
        {
            const int b  = tid >> 7;        // 8 groups of 128 threads
            const int rr = tid & 127;
            if (rr < nrows) {
                float* o = out + ((size_t)step * BATCH + b) * VOCAB + base;
                if (s_done[b]) o[rr] = (base + rr == PAD_ID) ? 1.f : 0.f;
                else           o[rr] = __fdividef(__expf(s_log[rr][b]), s_S[b]);
            }
        }
        cur = nxt;
    }
}

extern "C" void kernel_launch(void* const* d_in, const int* in_sizes, int n_in,
                              void* d_out, int out_size) {
    const float* hidden    = (const float*)d_in[0];
    const float* embedding = (const float*)d_in[1];
    const float* w_ih      = (const float*)d_in[2];
    const float* w_hh      = (const float*)d_in[3];
    const float* b_ih      = (const float*)d_in[4];
    const float* b_hh      = (const float*)d_in[5];
    const float* w_out     = (const float*)d_in[6];
    const float* b_out     = (const float*)d_in[7];
    float* out = (float*)d_out;
    (void)in_sizes; (void)n_in;

    const int lenseq = out_size / (BATCH * VOCAB);
    if (lenseq <= 0) return;

    decoder_init<<<16, 256>>>(hidden);
    decoder_main<<<NCTA, TPB>>>(embedding, w_ih, w_hh, b_ih, b_hh,
                                w_out, b_out, out, lenseq);
}

// round 10
// speedup vs baseline: 1.2799x; 1.0018x over previous
#include <cuda_runtime.h>
#include <math.h>

// Greedy-collapsed beam search, persistent-grid decoder.
// Round-8 restructure: TPB=1024 (occ 50%), B1 = 4 rows/warp with packed
// fma.rn.f32x2 over batch pairs + fold-butterfly reduction, GRU reads
// weights exactly once per step (j-per-warp-half), max-free softmax.

#define NCTA  148
#define TPB   1024
#define VOCAB 16000
#define EDIM  256
#define HDIM  512
#define BATCH 8
#define PAD_ID 0
#define SOS_ID 1
#define EOS_ID 2

typedef unsigned long long ull;

__device__ float    g_h[2][BATCH * HDIM];
__device__ float4   g_part[NCTA][BATCH];   // x=max, y=sumexp(abs), z=argmax idx bits
__device__ unsigned g_bar;

__global__ void decoder_init(const float* __restrict__ hidden) {
    int t = blockIdx.x * blockDim.x + threadIdx.x;
    if (t < BATCH * HDIM) g_h[0][t] = hidden[t];
    if (t == 0) g_bar = 0u;
}

__device__ __forceinline__ ull fma2(ull a, ull b, ull c) {
    ull d; asm("fma.rn.f32x2 %0, %1, %2, %3;" : "=l"(d) : "l"(a), "l"(b), "l"(c)); return d;
}
__device__ __forceinline__ ull add2(ull a, ull b) {
    ull d; asm("add.rn.f32x2 %0, %1, %2;" : "=l"(d) : "l"(a), "l"(b)); return d;
}
__device__ __forceinline__ ull bcast2(float x) {
    ull d; asm("mov.b64 %0, {%1, %1};" : "=l"(d) : "r"(__float_as_uint(x))); return d;
}

__device__ __forceinline__ void grid_sync(unsigned target) {
    __syncthreads();
    if (threadIdx.x == 0) {
        __threadfence();
        atomicAdd(&g_bar, 1u);
        while (*(volatile unsigned*)&g_bar < target) {}
        __threadfence();
    }
    __syncthreads();
}

// Stage h (4096 floats) into two smem layouts:
//   s_h03[d] = {h0[d],h1[d],h2[d],h3[d]}, s_h47 likewise  (for B1 packed loads)
//   s_hn[b*516 + d] = h[b][d]                              (for GRU float4 loads)
__device__ __forceinline__ void stage_h(const float* src, float4* s_h03, float4* s_h47,
                                        float* s_hn, int tid) {
    float4 v = __ldcg((const float4*)src + tid);   // tid in [0,1024): one float4 each
    const int b = tid >> 7;
    const int d = (tid & 127) * 4;
    *(float4*)&s_hn[b * 516 + d] = v;
    float* t03 = (b < 4) ? (float*)s_h03 : (float*)s_h47;
    const int bb = b & 3;
    t03[(d + 0) * 4 + bb] = v.x;
    t03[(d + 1) * 4 + bb] = v.y;
    t03[(d + 2) * 4 + bb] = v.z;
    t03[(d + 3) * 4 + bb] = v.w;
}

__global__ void __launch_bounds__(TPB, 1) decoder_main(
    const float* __restrict__ embedding,
    const float* __restrict__ w_ih,
    const float* __restrict__ w_hh,
    const float* __restrict__ b_ih,
    const float* __restrict__ b_hh,
    const float* __restrict__ w_out,
    const float* __restrict__ b_out,
    float* __restrict__ out,
    int lenseq)
{
    __shared__ float4 s_h03[HDIM];            // 8 KB
    __shared__ float4 s_h47[HDIM];            // 8 KB
    __shared__ float  s_hn[BATCH * 516];      // 16.1 KB (516 = pad for bank spread)
    __shared__ float  s_log[112][9];          // 4 KB, stride-9 = conflict-free
    __shared__ float  s_S[BATCH];
    __shared__ int    s_tok[BATCH], s_done[BATCH];

    const int tid  = threadIdx.x;
    const int wp   = tid >> 5;
    const int lane = tid & 31;
    const int cta  = blockIdx.x;
    const int base  = cta * 108 + (cta < 16 ? cta : 16);
    const int nrows = 108 + (cta < 16 ? 1 : 0);

    // GRU task: 1024 tasks = 512 j's x 2 batch-halves, spread across CTAs
    const int  task   = wp * NCTA + cta;
    const bool gru_on = task < 2 * HDIM;
    const int  gj     = task >> 1;
    const int  gb     = (task & 1) * 4 + (lane >> 3);  // batch
    const int  gg     = lane & 7;                       // dim group

    if (tid < BATCH) s_tok[tid] = SOS_ID;
    stage_h(g_h[0], s_h03, s_h47, s_hn, tid);
    __syncthreads();

    unsigned bt = 0;
    int cur = 0;

    for (int step = 0; step < lenseq; ++step) {
        const int nxt = cur ^ 1;

        // ================= Phase A: GRU (weights read once chip-wide) ========
        if (gru_on) {
            const int tok = s_tok[gb];
            float ir = 0.f, iz = 0.f, in_ = 0.f;
            const float4* e4  = (const float4*)(embedding + (size_t)tok * EDIM);
            const float4* air = (const float4*)(w_ih + (size_t)gj * EDIM);
            const float4* aiz = (const float4*)(w_ih + (size_t)(gj + HDIM) * EDIM);
            const float4* ain = (const float4*)(w_ih + (size_t)(gj + 2 * HDIM) * EDIM);
            #pragma unroll
            for (int it = 0; it < 8; ++it) {
                const int c = gg * 8 + it;
                float4 e = e4[c];
                float4 a = air[c]; ir  += e.x*a.x + e.y*a.y + e.z*a.z + e.w*a.w;
                float4 z = aiz[c]; iz  += e.x*z.x + e.y*z.y + e.z*z.z + e.w*z.w;
                float4 n = ain[c]; in_ += e.x*n.x + e.y*n.y + e.z*n.z + e.w*n.w;
            }
            float hr = 0.f, hz = 0.f, hn = 0.f;
            const float4* uhr = (const float4*)(w_hh + (size_t)gj * HDIM);
            const float4* uhz = (const float4*)(w_hh + (size_t)(gj + HDIM) * HDIM);
            const float4* uhn = (const float4*)(w_hh + (size_t)(gj + 2 * HDIM) * HDIM);
            const float*  hb  = s_hn + gb * 516;
            #pragma unroll 4
            for (int it = 0; it < 16; ++it) {
                const int c = gg * 16 + it;
                float4 h = *(const float4*)&hb[c * 4];
                float4 a = uhr[c]; hr += h.x*a.x + h.y*a.y + h.z*a.z + h.w*a.w;
                float4 z = uhz[c]; hz += h.x*z.x + h.y*z.y + h.z*z.z + h.w*z.w;
                float4 n = uhn[c]; hn += h.x*n.x + h.y*n.y + h.z*n.z + h.w*n.w;
            }
            #pragma unroll
            for (int off = 1; off < 8; off <<= 1) {
                ir  += __shfl_xor_sync(~0u, ir,  off);
                iz  += __shfl_xor_sync(~0u, iz,  off);
                in_ += __shfl_xor_sync(~0u, in_, off);
                hr  += __shfl_xor_sync(~0u, hr,  off);
                hz  += __shfl_xor_sync(~0u, hz,  off);
                hn  += __shfl_xor_sync(~0u, hn,  off);
            }
            if (gg == 0) {
                const float hold = hb[gj];
                float hv;
                if (tok == PAD_ID || tok == EOS_ID) {
                    hv = hold;
                } else {
                    const float rg = 1.f / (1.f + expf(-(ir + b_ih[gj]            + hr + b_hh[gj])));
                    const float zg = 1.f / (1.f + expf(-(iz + b_ih[gj + HDIM]     + hz + b_hh[gj + HDIM])));
                    const float ng = tanhf(in_ + b_ih[gj + 2 * HDIM] + rg * (hn + b_hh[gj + 2 * HDIM]));
                    hv = (1.f - zg) * ng + zg * hold;
                }
                g_h[nxt][gb * HDIM + gj] = hv;
            }
        }
        bt += NCTA; grid_sync(bt);

        // ================= Stage h(nxt) into smem ============================
        stage_h(g_h[nxt], s_h03, s_h47, s_hn, tid);
        __syncthreads();

        // ================= Phase B1: logits, 4 rows/warp, packed f32x2 =======
        {
            const int r0c = min(wp,      nrows - 1);
            const int r1c = min(wp + 32, nrows - 1);
            const int r2c = min(wp + 64, nrows - 1);
            const int r3c = min(wp + 96, nrows - 1);
            const float* w0 = w_out + (size_t)(base + r0c) * HDIM;
            const float* w1 = w_out + (size_t)(base + r1c) * HDIM;
            const float* w2 = w_out + (size_t)(base + r2c) * HDIM;
            const float* w3 = w_out + (size_t)(base + r3c) * HDIM;
            ull v[16];
            #pragma unroll
            for (int i = 0; i < 16; i++) v[i] = 0ull;
            #pragma unroll 4
            for (int k = 0; k < 16; k++) {
                const int d = k * 32 + lane;                       // coalesced dims
                const ulonglong2 hA = *(const ulonglong2*)&s_h03[d];  // {h01,h23}
                const ulonglong2 hB = *(const ulonglong2*)&s_h47[d];  // {h45,h67}
                ull wb;
                wb = bcast2(w0[d]);
                v[0]=fma2(wb,hA.x,v[0]);  v[1]=fma2(wb,hA.y,v[1]);
                v[2]=fma2(wb,hB.x,v[2]);  v[3]=fma2(wb,hB.y,v[3]);
                wb = bcast2(w1[d]);
                v[4]=fma2(wb,hA.x,v[4]);  v[5]=fma2(wb,hA.y,v[5]);
                v[6]=fma2(wb,hB.x,v[6]);  v[7]=fma2(wb,hB.y,v[7]);
                wb = bcast2(w2[d]);
                v[8]=fma2(wb,hA.x,v[8]);  v[9]=fma2(wb,hA.y,v[9]);
                v[10]=fma2(wb,hB.x,v[10]); v[11]=fma2(wb,hB.y,v[11]);
                wb = bcast2(w3[d]);
                v[12]=fma2(wb,hA.x,v[12]); v[13]=fma2(wb,hA.y,v[13]);
                v[14]=fma2(wb,hB.x,v[14]); v[15]=fma2(wb,hB.y,v[15]);
            }
            // fold-butterfly: 16 accs x 32 lanes -> each lane-pair one total
            #pragma unroll
            for (int i = 0; i < 8; i++) {
                ull give = (lane & 16) ? v[i] : v[i + 8];
                ull keep = (lane & 16) ? v[i + 8] : v[i];
                v[i] = add2(keep, __shfl_xor_sync(~0u, give, 16));
            }
            #pragma unroll
            for (int i = 0; i < 4; i++) {
                ull give = (lane & 8) ? v[i] : v[i + 4];
                ull keep = (lane & 8) ? v[i + 4] : v[i];
                v[i] = add2(keep, __shfl_xor_sync(~0u, give, 8));
            }
            #pragma unroll
            for (int i = 0; i < 2; i++) {
                ull give = (lane & 4) ? v[i] : v[i + 2];
                ull keep = (lane & 4) ? v[i + 2] : v[i];
                v[i] = add2(keep, __shfl_xor_sync(~0u, give, 4));
            }
            {
                ull give = (lane & 2) ? v[0] : v[1];
                ull keep = (lane & 2) ? v[1] : v[0];
                v[0] = add2(keep, __shfl_xor_sync(~0u, give, 2));
            }
            v[0] = add2(v[0], __shfl_xor_sync(~0u, v[0], 1));
            // lane l holds total for row index (l>>3)&3, batch-pair (l>>1)&3
            if (!(lane & 1)) {
                const int i = (lane >> 3) & 3;
                const int p = (lane >> 1) & 3;
                const int r = wp + 32 * i;
                if (r < nrows) {
                    const float bo = b_out[base + r];
                    const float2 lv = *(float2*)&v[0];
                    s_log[r][2 * p]     = lv.x + bo;
                    s_log[r][2 * p + 1] = lv.y + bo;
                }
            }
        }
        __syncthreads();

        // ============ per-CTA partial: abs-sumexp + argmax (warps 0-7) =======
        if (wp < BATCH) {
            const int b = wp;
            float m = -INFINITY, s = 0.f; int mi = 0x7fffffff;
            for (int r = lane; r < nrows; r += 32) {
                const float vv = s_log[r][b];
                s += __expf(vv);
                if (vv > m) { m = vv; mi = base + r; }
            }
            #pragma unroll
            for (int off = 16; off; off >>= 1) {
                const float om = __shfl_xor_sync(~0u, m, off);
                const int   oi = __shfl_xor_sync(~0u, mi, off);
                s += __shfl_xor_sync(~0u, s, off);
                if (om > m || (om == m && oi < mi)) { m = om; mi = oi; }
            }
            if (lane == 0) g_part[cta][b] = make_float4(m, s, __int_as_float(mi), 0.f);
        }
        bt += NCTA; grid_sync(bt);

        // ============ Phase B2: global reduce (redundant per CTA) ============
        if (wp < BATCH) {
            const int b = wp;
            float m = -INFINITY, S = 0.f; int mi = 0x7fffffff;
            for (int c = lane; c < NCTA; c += 32) {
                const float4 pr = __ldcg(&g_part[c][b]);
                S += pr.y;
                const int oi = __float_as_int(pr.z);
                if (pr.x > m || (pr.x == m && oi < mi)) { m = pr.x; mi = oi; }
            }
            #pragma unroll
            for (int off = 16; off; off >>= 1) {
                const float om = __shfl_xor_sync(~0u, m, off);
                const int   oi = __shfl_xor_sync(~0u, mi, off);
                S += __shfl_xor_sync(~0u, S, off);
                if (om > m || (om == m && oi < mi)) { m = om; mi = oi; }
            }
            if (lane == 0) {
                const int old = s_tok[b];
                const int d = (old == PAD_ID) | (old == EOS_ID);
                s_done[b] = d;
                s_S[b]    = S;
                s_tok[b]  = d ? PAD_ID : mi;    // done -> PAD forever
            }
        }
        __syncthreads();

        // ============ Phase C: coalesced probability write ===================
        {
            const int b  = tid >> 7;        // 8 groups of 128 threads
            const int rr = tid & 127;
            if (rr < nrows) {
                float* o = out + ((size_t)step * BATCH + b) * VOCAB + base;
                if (s_done[b]) o[rr] = (base + rr == PAD_ID) ? 1.f : 0.f;
                else           o[rr] = __fdividef(__expf(s_log[rr][b]), s_S[b]);
            }
        }
        cur = nxt;
    }
}

extern "C" void kernel_launch(void* const* d_in, const int* in_sizes, int n_in,
                              void* d_out, int out_size) {
    const float* hidden    = (const float*)d_in[0];
    const float* embedding = (const float*)d_in[1];
    const float* w_ih      = (const float*)d_in[2];
    const float* w_hh      = (const float*)d_in[3];
    const float* b_ih      = (const float*)d_in[4];
    const float* b_hh      = (const float*)d_in[5];
    const float* w_out     = (const float*)d_in[6];
    const float* b_out     = (const float*)d_in[7];
    float* out = (float*)d_out;
    (void)in_sizes; (void)n_in;

    const int lenseq = out_size / (BATCH * VOCAB);
    if (lenseq <= 0) return;

    decoder_init<<<16, 256>>>(hidden);
    decoder_main<<<NCTA, TPB>>>(embedding, w_ih, w_hh, b_ih, b_hh,
                                w_out, b_out, out, lenseq);
}